// round 15
// baseline (speedup 1.0000x reference)
#include <cuda_runtime.h>
#include <cuda_fp16.h>
#include <cstdint>

typedef uint32_t u32;

#define BB 2
#define HH 16
#define SS 2048
#define DD 64
#define QT 128
#define KT 128
#define NKB (SS/KT)
#define NTH 256
#define CEXP 0.18033688011112042f   // 0.125 * log2(e)
#define MASKED_ARG (-1.0e4f)        // ex2.ftz -> exactly 0
#define KVELEM (BB*HH*SS*DD)        // 4,194,304

// kernel A: 3-stage K pipeline (16KB/stage)
#define A_STAGE 16384
#define A_SMEM  (3*A_STAGE)          // 49152
// kernel B: double-buffered K+V (32KB/stage)
#define OFF_VH 16384
#define BUFSZ  32768
#define B_SMEM 65536

__device__ u32   g_maskbits[SS * SS / 32];             // 512 KB
__device__ uint4 g_kh[KVELEM / 8], g_vh[KVELEM / 8];   // fp16 K,V (8 MB each)
__device__ float g_linv[BB * HH * SS];                 // -log2(rowsum), 256 KB

__global__ void pack_mask_kernel(const int* __restrict__ mask) {
    int tid = blockIdx.x * blockDim.x + threadIdx.x;
    const int4* m4 = (const int4*)mask + (size_t)tid * 8;
    u32 bits = 0;
    #pragma unroll
    for (int j = 0; j < 8; j++) {
        int4 v = m4[j];
        bits |= (v.x ? 1u : 0u) << (4 * j);
        bits |= (v.y ? 1u : 0u) << (4 * j + 1);
        bits |= (v.z ? 1u : 0u) << (4 * j + 2);
        bits |= (v.w ? 1u : 0u) << (4 * j + 3);
    }
    g_maskbits[tid] = bits;
}

__device__ __forceinline__ float ex2f(float x) {
    float r; asm("ex2.approx.ftz.f32 %0, %1;" : "=f"(r) : "f"(x)); return r;
}
__device__ __forceinline__ float lg2f(float x) {
    float r; asm("lg2.approx.f32 %0, %1;" : "=f"(r) : "f"(x)); return r;
}
__device__ __forceinline__ u32 packh(float x, float y) {
    __half2 h = __floats2half2_rn(x, y);
    return *reinterpret_cast<u32*>(&h);
}

__global__ void split_kv_kernel(const float* __restrict__ K, const float* __restrict__ V) {
    int i = blockIdx.x * blockDim.x + threadIdx.x;
    const float4* k4 = (const float4*)K;
    const float4* v4 = (const float4*)V;
    float4 a = k4[2 * i], b = k4[2 * i + 1];
    g_kh[i] = make_uint4(packh(a.x, a.y), packh(a.z, a.w), packh(b.x, b.y), packh(b.z, b.w));
    a = v4[2 * i]; b = v4[2 * i + 1];
    g_vh[i] = make_uint4(packh(a.x, a.y), packh(a.z, a.w), packh(b.x, b.y), packh(b.z, b.w));
}

__device__ __forceinline__ void mma_f16(float c[4], const u32 a[4], u32 b0, u32 b1) {
    asm volatile("mma.sync.aligned.m16n8k16.row.col.f32.f16.f16.f32 "
        "{%0,%1,%2,%3}, {%4,%5,%6,%7}, {%8,%9}, {%0,%1,%2,%3};"
        : "+f"(c[0]), "+f"(c[1]), "+f"(c[2]), "+f"(c[3])
        : "r"(a[0]), "r"(a[1]), "r"(a[2]), "r"(a[3]), "r"(b0), "r"(b1));
}
__device__ __forceinline__ void ldsm4(u32 r[4], u32 a) {
    asm volatile("ldmatrix.sync.aligned.m8n8.x4.shared.b16 {%0,%1,%2,%3}, [%4];"
        : "=r"(r[0]), "=r"(r[1]), "=r"(r[2]), "=r"(r[3]) : "r"(a));
}
__device__ __forceinline__ void ldsm4t(u32 r[4], u32 a) {
    asm volatile("ldmatrix.sync.aligned.m8n8.x4.trans.shared.b16 {%0,%1,%2,%3}, [%4];"
        : "=r"(r[0]), "=r"(r[1]), "=r"(r[2]), "=r"(r[3]) : "r"(a));
}
__device__ __forceinline__ void cpa16(u32 dst, const void* src) {
    asm volatile("cp.async.cg.shared.global [%0], [%1], 16;" :: "r"(dst), "l"(src));
}
#define CP_COMMIT() asm volatile("cp.async.commit_group;" ::: "memory")
#define CP_WAIT1()  asm volatile("cp.async.wait_group 1;" ::: "memory")
#define CP_WAIT0()  asm volatile("cp.async.wait_group 0;" ::: "memory")

__device__ __forceinline__ u32 swz_dst(int i) {
    return (u32)(((i >> 3) << 7) + (((i & 7) ^ ((i >> 3) & 7)) << 4));
}

// load one 16-row Q fragment set (fp16 hi)
__device__ __forceinline__ void load_q_frags(u32 qh[4][4], const float* Qp,
                                             int gr, int c) {
    #pragma unroll
    for (int ks = 0; ks < 4; ks++) {
        const float* r0 = Qp + gr * DD + ks * 16 + 2 * c;
        const float* r1 = r0 + 8 * DD;
        float2 f00 = *(const float2*)(r0);
        float2 f10 = *(const float2*)(r1);
        float2 f01 = *(const float2*)(r0 + 8);
        float2 f11 = *(const float2*)(r1 + 8);
        qh[ks][0] = packh(f00.x, f00.y);
        qh[ks][1] = packh(f10.x, f10.y);
        qh[ks][2] = packh(f01.x, f01.y);
        qh[ks][3] = packh(f11.x, f11.y);
    }
}

// =============== KERNEL A: row sums -> g_linv (unchanged from R14) ===============
__global__ void __launch_bounds__(NTH, 4)
pass1_kernel(const float* __restrict__ Q) {
    extern __shared__ char sm[];
    u32 sb;
    asm("{ .reg .u64 t; cvta.to.shared.u64 t, %1; cvt.u32.u64 %0, t; }" : "=r"(sb) : "l"(sm));

    const int t = threadIdx.x;
    const int w = t >> 5, l = t & 31;
    const int gr = l >> 2, c = l & 3;

    const int qblk = blockIdx.x >> 5;
    const int bh   = blockIdx.x & 31;
    const int q0   = qblk * QT;
    const int qw0  = w * 16;

    const uint4* pkh = g_kh + (size_t)bh * (SS * DD / 8);

    #pragma unroll
    for (int st = 0; st < 2; st++) {
        #pragma unroll
        for (int j = 0; j < 4; j++) {
            int i = t + j * NTH;
            cpa16(sb + (u32)(st * A_STAGE) + swz_dst(i), pkh + (size_t)st * 1024 + i);
        }
        CP_COMMIT();
    }

    u32 qh[4][4];
    load_q_frags(qh, Q + ((size_t)bh * SS + q0 + qw0) * DD, gr, c);

    const int mrow0 = q0 + qw0 + gr;
    const u32* mw0 = g_maskbits + (size_t)mrow0 * (SS / 32);
    const u32* mw1 = mw0 + 8 * (SS / 32);
    const u32 bm0 = 1u << (2 * c), bm1 = 2u << (2 * c);
    const u32 bm8 = bm0 << 8,      bm9 = bm1 << 8;

    const int rl  = ((l >> 4) & 1) * 8 + (l & 7);
    const int clk = (l >> 3) & 1;
    const u32 lkA = (u32)(rl << 7), lks = (u32)(rl & 7);

    float l0 = 0.f, l1 = 0.f;

    for (int kb = 0; kb < NKB; kb++) {
        const u32 kbase = sb + (u32)((kb % 3) * A_STAGE);
        if (kb >= NKB - 2) { CP_WAIT0(); } else { CP_WAIT1(); }
        __syncthreads();
        if (kb + 2 < NKB) {
            #pragma unroll
            for (int j = 0; j < 4; j++) {
                int i = t + j * NTH;
                cpa16(sb + (u32)(((kb + 2) % 3) * A_STAGE) + swz_dst(i),
                      pkh + (size_t)(kb + 2) * 1024 + i);
            }
            CP_COMMIT();
        }

        #pragma unroll
        for (int jp = 0; jp < 8; jp++) {
            float s0[4] = {0,0,0,0}, s1[4] = {0,0,0,0};
            #pragma unroll
            for (int ks = 0; ks < 4; ks++) {
                u32 kf[4];
                ldsm4(kf, kbase + (u32)(jp * 2048) + lkA
                          + ((((u32)(ks << 1) | clk) ^ lks) << 4));
                mma_f16(s0, qh[ks], kf[0], kf[1]);
                mma_f16(s1, qh[ks], kf[2], kf[3]);
            }
            u32 w0 = mw0[kb * 4 + (jp >> 1)];
            u32 w1 = mw1[kb * 4 + (jp >> 1)];
            u32 W0 = (jp & 1) ? (w0 >> 16) : w0;
            u32 W1 = (jp & 1) ? (w1 >> 16) : w1;
            float a0 = (W0 & bm0) ? s0[0] * CEXP : MASKED_ARG;
            float a1 = (W0 & bm1) ? s0[1] * CEXP : MASKED_ARG;
            float a2 = (W1 & bm0) ? s0[2] * CEXP : MASKED_ARG;
            float a3 = (W1 & bm1) ? s0[3] * CEXP : MASKED_ARG;
            float a4 = (W0 & bm8) ? s1[0] * CEXP : MASKED_ARG;
            float a5 = (W0 & bm9) ? s1[1] * CEXP : MASKED_ARG;
            float a6 = (W1 & bm8) ? s1[2] * CEXP : MASKED_ARG;
            float a7 = (W1 & bm9) ? s1[3] * CEXP : MASKED_ARG;
            l0 += ex2f(a0) + ex2f(a1);
            l1 += ex2f(a2) + ex2f(a3);
            l0 += ex2f(a4) + ex2f(a5);
            l1 += ex2f(a6) + ex2f(a7);
        }
    }
    l0 += __shfl_xor_sync(0xffffffffu, l0, 1);
    l0 += __shfl_xor_sync(0xffffffffu, l0, 2);
    l1 += __shfl_xor_sync(0xffffffffu, l1, 1);
    l1 += __shfl_xor_sync(0xffffffffu, l1, 2);
    if (c == 0) {
        g_linv[(size_t)bh * SS + q0 + qw0 + gr]     = -lg2f(l0);
        g_linv[(size_t)bh * SS + q0 + qw0 + gr + 8] = -lg2f(l1);
    }
}

// =============== KERNEL B: P write + O = P@V (4 mg x 2 key-halves) ===============
__global__ void __launch_bounds__(NTH, 1)
pass2_kernel(const float* __restrict__ Q,
             float* __restrict__ Out, float* __restrict__ Prob) {
    extern __shared__ char sm[];
    u32 sb;
    asm("{ .reg .u64 t; cvta.to.shared.u64 t, %1; cvt.u32.u64 %0, t; }" : "=r"(sb) : "l"(sm));

    const int t = threadIdx.x;
    const int w = t >> 5, l = t & 31;
    const int gr = l >> 2, c = l & 3;
    const int mg = w >> 1;            // 0..3: rows mg*32..+31
    const int kh = w & 1;             // 0..1: keys kh*64..+63 within each kb

    const int qblk = blockIdx.x >> 5;
    const int bh   = blockIdx.x & 31;
    const int q0   = qblk * QT;
    const int rb   = mg * 32;

    const size_t bhbase = (size_t)bh * (SS * DD / 8);
    const uint4* pkh = g_kh + bhbase;
    const uint4* pvh = g_vh + bhbase;

    // prologue fills (K + V, stage 0)
    #pragma unroll
    for (int j = 0; j < 4; j++) {
        int i = t + j * NTH;
        u32 d = swz_dst(i);
        cpa16(sb + d, pkh + i);
        cpa16(sb + OFF_VH + d, pvh + i);
    }
    CP_COMMIT();

    // Q fragments for 32 rows (2 m-frags)
    u32 qh[2][4][4];
    #pragma unroll
    for (int m = 0; m < 2; m++)
        load_q_frags(qh[m], Q + ((size_t)bh * SS + q0 + rb + m * 16) * DD, gr, c);

    // per-row (j = 2m + r8) mask pointers, linv, Prob pointers
    const u32* mwp[4];
    float linv_[4];
    float* prj[4];
    const size_t gq0 = (size_t)bh * SS + q0 + rb;
    #pragma unroll
    for (int j = 0; j < 4; j++) {
        int rloc = (j >> 1) * 16 + (j & 1) * 8 + gr;
        mwp[j]  = g_maskbits + (size_t)(q0 + rb + rloc) * (SS / 32);
        linv_[j] = g_linv[gq0 + rloc];
        prj[j]  = Prob + (gq0 + rloc) * SS + kh * 64 + 2 * c;
    }

    const u32 bm0 = 1u << (2 * c), bm1 = 2u << (2 * c);
    const u32 bm8 = bm0 << 8,      bm9 = bm1 << 8;

    const int rl  = ((l >> 4) & 1) * 8 + (l & 7);
    const int clk = (l >> 3) & 1;
    const u32 lks = (u32)(rl & 7);
    const int rv  = ((l >> 3) & 1) * 8 + (l & 7);
    const int cv  = (l >> 4) & 1;
    const u32 lvs = (u32)(rv & 7);

    float oacc[2][8][4];
    #pragma unroll
    for (int m = 0; m < 2; m++)
        #pragma unroll
        for (int nf = 0; nf < 8; nf++)
            #pragma unroll
            for (int x = 0; x < 4; x++) oacc[m][nf][x] = 0.f;

    for (int kb = 0; kb < NKB; kb++) {
        const u32 bufA = sb + (u32)((kb & 1) * BUFSZ);
        const u32 bufB = sb + (u32)(((kb + 1) & 1) * BUFSZ);
        CP_WAIT0();
        __syncthreads();
        if (kb + 1 < NKB) {
            #pragma unroll
            for (int j = 0; j < 4; j++) {
                int i = t + j * NTH;
                const size_t gi = (size_t)(kb + 1) * 1024 + i;
                u32 d = swz_dst(i);
                cpa16(bufB + d, pkh + gi);
                cpa16(bufB + OFF_VH + d, pvh + gi);
            }
            CP_COMMIT();
        }

        #pragma unroll
        for (int jp = 0; jp < 4; jp++) {
            const u32 rowK = (u32)((kh * 64 + jp * 16 + rl) << 7);
            const u32 rowV = (u32)((kh * 64 + jp * 16 + rv) << 7);

            // K fragments once, reused for both m-frags
            u32 kf[4][4];
            #pragma unroll
            for (int ks = 0; ks < 4; ks++)
                ldsm4(kf[ks], bufA + rowK + ((((u32)(ks << 1) | clk) ^ lks) << 4));

            float s[2][2][4];
            #pragma unroll
            for (int m = 0; m < 2; m++)
                #pragma unroll
                for (int n = 0; n < 2; n++)
                    #pragma unroll
                    for (int x = 0; x < 4; x++) s[m][n][x] = 0.f;
            #pragma unroll
            for (int ks = 0; ks < 4; ks++)
                #pragma unroll
                for (int m = 0; m < 2; m++) {
                    mma_f16(s[m][0], qh[m][ks], kf[ks][0], kf[ks][1]);
                    mma_f16(s[m][1], qh[m][ks], kf[ks][2], kf[ks][3]);
                }

            // V fragments once, reused for both m-frags (independent of exp chain)
            u32 vf[4][4];
            #pragma unroll
            for (int op = 0; op < 4; op++)
                ldsm4t(vf[op], bufA + OFF_VH + rowV
                               + ((((u32)(op << 1) | cv) ^ lvs) << 4));

            const int wcol = kb * 4 + kh * 2 + (jp >> 1);
            u32 aH[2][4];
            #pragma unroll
            for (int m = 0; m < 2; m++)
                #pragma unroll
                for (int r8 = 0; r8 < 2; r8++) {
                    int j = 2 * m + r8;
                    u32 wv = mwp[j][wcol];
                    u32 W = (jp & 1) ? (wv >> 16) : wv;
                    float a0 = (W & bm0) ? fmaf(s[m][0][2*r8],   CEXP, linv_[j]) : MASKED_ARG;
                    float a1 = (W & bm1) ? fmaf(s[m][0][2*r8+1], CEXP, linv_[j]) : MASKED_ARG;
                    float a2 = (W & bm8) ? fmaf(s[m][1][2*r8],   CEXP, linv_[j]) : MASKED_ARG;
                    float a3 = (W & bm9) ? fmaf(s[m][1][2*r8+1], CEXP, linv_[j]) : MASKED_ARG;
                    float e0 = ex2f(a0), e1 = ex2f(a1);
                    float e2 = ex2f(a2), e3 = ex2f(a3);
                    float* pp = prj[j] + (size_t)kb * KT + jp * 16;
                    __stcs((float2*)pp,       make_float2(e0, e1));
                    __stcs((float2*)(pp + 8), make_float2(e2, e3));
                    aH[m][r8]     = packh(e0, e1);
                    aH[m][2 + r8] = packh(e2, e3);
                }

            #pragma unroll
            for (int m = 0; m < 2; m++)
                #pragma unroll
                for (int op = 0; op < 4; op++) {
                    mma_f16(oacc[m][2*op],   aH[m], vf[op][0], vf[op][1]);
                    mma_f16(oacc[m][2*op+1], aH[m], vf[op][2], vf[op][3]);
                }
        }
    }

    // ---- O reduction over the 2 key-halves (row stride 72 floats: conflict-free) ----
    __syncthreads();
    float* red = (float*)sm + (size_t)mg * (32 * 72);
    if (kh == 1) {
        #pragma unroll
        for (int m = 0; m < 2; m++)
            #pragma unroll
            for (int nf = 0; nf < 8; nf++)
                #pragma unroll
                for (int r8 = 0; r8 < 2; r8++)
                    *(float2*)(red + (m*16 + r8*8 + gr) * 72 + nf*8 + 2*c) =
                        make_float2(oacc[m][nf][2*r8], oacc[m][nf][2*r8+1]);
    }
    __syncthreads();
    if (kh == 0) {
        #pragma unroll
        for (int m = 0; m < 2; m++)
            #pragma unroll
            for (int nf = 0; nf < 8; nf++)
                #pragma unroll
                for (int r8 = 0; r8 < 2; r8++) {
                    float2 v = *(const float2*)(red + (m*16 + r8*8 + gr) * 72 + nf*8 + 2*c);
                    *(float2*)(Out + (gq0 + m*16 + r8*8 + gr) * DD + nf*8 + 2*c) =
                        make_float2(oacc[m][nf][2*r8] + v.x, oacc[m][nf][2*r8+1] + v.y);
                }
    }
}

extern "C" void kernel_launch(void* const* d_in, const int* in_sizes, int n_in,
                              void* d_out, int out_size) {
    const float* q    = (const float*)d_in[0];
    const float* k    = (const float*)d_in[1];
    const float* v    = (const float*)d_in[2];
    const int*   mask = (const int*)d_in[3];

    float* out  = (float*)d_out;                          // [B,H,S,D]
    float* prob = out + (size_t)BB * HH * SS * DD;        // [B,H,S,S]

    pack_mask_kernel<<<(SS * SS / 32) / NTH, NTH>>>(mask);
    split_kv_kernel<<<(KVELEM / 8) / NTH, NTH>>>(k, v);

    cudaFuncSetAttribute(pass1_kernel,
                         cudaFuncAttributeMaxDynamicSharedMemorySize, A_SMEM);
    cudaFuncSetAttribute(pass2_kernel,
                         cudaFuncAttributeMaxDynamicSharedMemorySize, B_SMEM);

    dim3 grid(BB * HH * (SS / QT));   // 512 CTAs
    pass1_kernel<<<grid, NTH, A_SMEM>>>(q);
    pass2_kernel<<<grid, NTH, B_SMEM>>>(q, out, prob);    // launch #6 -> profiled
}

// round 16
// speedup vs baseline: 1.1130x; 1.1130x over previous
#include <cuda_runtime.h>
#include <cuda_fp16.h>
#include <cstdint>

typedef uint32_t u32;

#define BB 2
#define HH 16
#define SS 2048
#define DD 64
#define QT 128
#define KT 128
#define NKB (SS/KT)
#define NTH 256
#define CEXP 0.18033688011112042f   // 0.125 * log2(e)
#define MASKED_ARG (-1.0e4f)        // ex2.ftz -> exactly 0
#define KVELEM (BB*HH*SS*DD)        // 4,194,304

// kernel A: 3-stage K pipeline (16KB/stage)
#define A_STAGE 16384
#define A_SMEM  (3*A_STAGE)          // 49152
// kernel B: double-buffered K+V (32KB/stage) + fp16 P tile (32KB)
#define OFF_VH 16384
#define BUFSZ  32768
#define PT_OFF 65536
#define B_SMEM (PT_OFF + 32768)      // 98304

__device__ u32   g_maskbits[SS * SS / 32];             // 512 KB
__device__ uint4 g_kh[KVELEM / 8], g_vh[KVELEM / 8];   // fp16 K,V (8 MB each)
__device__ float g_linv[BB * HH * SS];                 // -log2(rowsum), 256 KB

__global__ void pack_mask_kernel(const int* __restrict__ mask) {
    int tid = blockIdx.x * blockDim.x + threadIdx.x;
    const int4* m4 = (const int4*)mask + (size_t)tid * 8;
    u32 bits = 0;
    #pragma unroll
    for (int j = 0; j < 8; j++) {
        int4 v = m4[j];
        bits |= (v.x ? 1u : 0u) << (4 * j);
        bits |= (v.y ? 1u : 0u) << (4 * j + 1);
        bits |= (v.z ? 1u : 0u) << (4 * j + 2);
        bits |= (v.w ? 1u : 0u) << (4 * j + 3);
    }
    g_maskbits[tid] = bits;
}

__device__ __forceinline__ float ex2f(float x) {
    float r; asm("ex2.approx.ftz.f32 %0, %1;" : "=f"(r) : "f"(x)); return r;
}
__device__ __forceinline__ float lg2f(float x) {
    float r; asm("lg2.approx.f32 %0, %1;" : "=f"(r) : "f"(x)); return r;
}
__device__ __forceinline__ u32 packh(float x, float y) {
    __half2 h = __floats2half2_rn(x, y);
    return *reinterpret_cast<u32*>(&h);
}

__global__ void split_kv_kernel(const float* __restrict__ K, const float* __restrict__ V) {
    int i = blockIdx.x * blockDim.x + threadIdx.x;
    const float4* k4 = (const float4*)K;
    const float4* v4 = (const float4*)V;
    float4 a = k4[2 * i], b = k4[2 * i + 1];
    g_kh[i] = make_uint4(packh(a.x, a.y), packh(a.z, a.w), packh(b.x, b.y), packh(b.z, b.w));
    a = v4[2 * i]; b = v4[2 * i + 1];
    g_vh[i] = make_uint4(packh(a.x, a.y), packh(a.z, a.w), packh(b.x, b.y), packh(b.z, b.w));
}

__device__ __forceinline__ void mma_f16(float c[4], const u32 a[4], u32 b0, u32 b1) {
    asm volatile("mma.sync.aligned.m16n8k16.row.col.f32.f16.f16.f32 "
        "{%0,%1,%2,%3}, {%4,%5,%6,%7}, {%8,%9}, {%0,%1,%2,%3};"
        : "+f"(c[0]), "+f"(c[1]), "+f"(c[2]), "+f"(c[3])
        : "r"(a[0]), "r"(a[1]), "r"(a[2]), "r"(a[3]), "r"(b0), "r"(b1));
}
__device__ __forceinline__ void ldsm4(u32 r[4], u32 a) {
    asm volatile("ldmatrix.sync.aligned.m8n8.x4.shared.b16 {%0,%1,%2,%3}, [%4];"
        : "=r"(r[0]), "=r"(r[1]), "=r"(r[2]), "=r"(r[3]) : "r"(a));
}
__device__ __forceinline__ void ldsm4t(u32 r[4], u32 a) {
    asm volatile("ldmatrix.sync.aligned.m8n8.x4.trans.shared.b16 {%0,%1,%2,%3}, [%4];"
        : "=r"(r[0]), "=r"(r[1]), "=r"(r[2]), "=r"(r[3]) : "r"(a));
}
__device__ __forceinline__ void cpa16(u32 dst, const void* src) {
    asm volatile("cp.async.cg.shared.global [%0], [%1], 16;" :: "r"(dst), "l"(src));
}
#define CP_COMMIT() asm volatile("cp.async.commit_group;" ::: "memory")
#define CP_WAIT1()  asm volatile("cp.async.wait_group 1;" ::: "memory")
#define CP_WAIT0()  asm volatile("cp.async.wait_group 0;" ::: "memory")

__device__ __forceinline__ u32 swz_dst(int i) {
    return (u32)(((i >> 3) << 7) + (((i & 7) ^ ((i >> 3) & 7)) << 4));
}

// load one 16-row Q fragment set (fp16 hi)
__device__ __forceinline__ void load_q_frags(u32 qh[4][4], const float* Qp,
                                             int gr, int c) {
    #pragma unroll
    for (int ks = 0; ks < 4; ks++) {
        const float* r0 = Qp + gr * DD + ks * 16 + 2 * c;
        const float* r1 = r0 + 8 * DD;
        float2 f00 = *(const float2*)(r0);
        float2 f10 = *(const float2*)(r1);
        float2 f01 = *(const float2*)(r0 + 8);
        float2 f11 = *(const float2*)(r1 + 8);
        qh[ks][0] = packh(f00.x, f00.y);
        qh[ks][1] = packh(f10.x, f10.y);
        qh[ks][2] = packh(f01.x, f01.y);
        qh[ks][3] = packh(f11.x, f11.y);
    }
}

// =============== KERNEL A: row sums -> g_linv (unchanged from R14) ===============
__global__ void __launch_bounds__(NTH, 4)
pass1_kernel(const float* __restrict__ Q) {
    extern __shared__ char sm[];
    u32 sb;
    asm("{ .reg .u64 t; cvta.to.shared.u64 t, %1; cvt.u32.u64 %0, t; }" : "=r"(sb) : "l"(sm));

    const int t = threadIdx.x;
    const int w = t >> 5, l = t & 31;
    const int gr = l >> 2, c = l & 3;

    const int qblk = blockIdx.x >> 5;
    const int bh   = blockIdx.x & 31;
    const int q0   = qblk * QT;
    const int qw0  = w * 16;

    const uint4* pkh = g_kh + (size_t)bh * (SS * DD / 8);

    #pragma unroll
    for (int st = 0; st < 2; st++) {
        #pragma unroll
        for (int j = 0; j < 4; j++) {
            int i = t + j * NTH;
            cpa16(sb + (u32)(st * A_STAGE) + swz_dst(i), pkh + (size_t)st * 1024 + i);
        }
        CP_COMMIT();
    }

    u32 qh[4][4];
    load_q_frags(qh, Q + ((size_t)bh * SS + q0 + qw0) * DD, gr, c);

    const int mrow0 = q0 + qw0 + gr;
    const u32* mw0 = g_maskbits + (size_t)mrow0 * (SS / 32);
    const u32* mw1 = mw0 + 8 * (SS / 32);
    const u32 bm0 = 1u << (2 * c), bm1 = 2u << (2 * c);
    const u32 bm8 = bm0 << 8,      bm9 = bm1 << 8;

    const int rl  = ((l >> 4) & 1) * 8 + (l & 7);
    const int clk = (l >> 3) & 1;
    const u32 lkA = (u32)(rl << 7), lks = (u32)(rl & 7);

    float l0 = 0.f, l1 = 0.f;

    for (int kb = 0; kb < NKB; kb++) {
        const u32 kbase = sb + (u32)((kb % 3) * A_STAGE);
        if (kb >= NKB - 2) { CP_WAIT0(); } else { CP_WAIT1(); }
        __syncthreads();
        if (kb + 2 < NKB) {
            #pragma unroll
            for (int j = 0; j < 4; j++) {
                int i = t + j * NTH;
                cpa16(sb + (u32)(((kb + 2) % 3) * A_STAGE) + swz_dst(i),
                      pkh + (size_t)(kb + 2) * 1024 + i);
            }
            CP_COMMIT();
        }

        #pragma unroll
        for (int jp = 0; jp < 8; jp++) {
            float s0[4] = {0,0,0,0}, s1[4] = {0,0,0,0};
            #pragma unroll
            for (int ks = 0; ks < 4; ks++) {
                u32 kf[4];
                ldsm4(kf, kbase + (u32)(jp * 2048) + lkA
                          + ((((u32)(ks << 1) | clk) ^ lks) << 4));
                mma_f16(s0, qh[ks], kf[0], kf[1]);
                mma_f16(s1, qh[ks], kf[2], kf[3]);
            }
            u32 w0 = mw0[kb * 4 + (jp >> 1)];
            u32 w1 = mw1[kb * 4 + (jp >> 1)];
            u32 W0 = (jp & 1) ? (w0 >> 16) : w0;
            u32 W1 = (jp & 1) ? (w1 >> 16) : w1;
            float a0 = (W0 & bm0) ? s0[0] * CEXP : MASKED_ARG;
            float a1 = (W0 & bm1) ? s0[1] * CEXP : MASKED_ARG;
            float a2 = (W1 & bm0) ? s0[2] * CEXP : MASKED_ARG;
            float a3 = (W1 & bm1) ? s0[3] * CEXP : MASKED_ARG;
            float a4 = (W0 & bm8) ? s1[0] * CEXP : MASKED_ARG;
            float a5 = (W0 & bm9) ? s1[1] * CEXP : MASKED_ARG;
            float a6 = (W1 & bm8) ? s1[2] * CEXP : MASKED_ARG;
            float a7 = (W1 & bm9) ? s1[3] * CEXP : MASKED_ARG;
            l0 += ex2f(a0) + ex2f(a1);
            l1 += ex2f(a2) + ex2f(a3);
            l0 += ex2f(a4) + ex2f(a5);
            l1 += ex2f(a6) + ex2f(a7);
        }
    }
    l0 += __shfl_xor_sync(0xffffffffu, l0, 1);
    l0 += __shfl_xor_sync(0xffffffffu, l0, 2);
    l1 += __shfl_xor_sync(0xffffffffu, l1, 1);
    l1 += __shfl_xor_sync(0xffffffffu, l1, 2);
    if (c == 0) {
        g_linv[(size_t)bh * SS + q0 + qw0 + gr]     = -lg2f(l0);
        g_linv[(size_t)bh * SS + q0 + qw0 + gr + 8] = -lg2f(l1);
    }
}

// =============== KERNEL B: P (smem-staged, coalesced) + O = P@V ===============
__global__ void __launch_bounds__(NTH, 2)
pass2_kernel(const float* __restrict__ Q,
             float* __restrict__ Out, float* __restrict__ Prob) {
    extern __shared__ char sm[];
    u32 sb;
    asm("{ .reg .u64 t; cvta.to.shared.u64 t, %1; cvt.u32.u64 %0, t; }" : "=r"(sb) : "l"(sm));

    const int t = threadIdx.x;
    const int w = t >> 5, l = t & 31;
    const int gr = l >> 2, c = l & 3;

    const int qblk = blockIdx.x >> 5;
    const int bh   = blockIdx.x & 31;
    const int q0   = qblk * QT;
    const int qw0  = w * 16;

    const size_t bhbase = (size_t)bh * (SS * DD / 8);
    const uint4* pkh = g_kh + bhbase;
    const uint4* pvh = g_vh + bhbase;

    // prologue fills (K + V, stage 0)
    #pragma unroll
    for (int j = 0; j < 4; j++) {
        int i = t + j * NTH;
        u32 d = swz_dst(i);
        cpa16(sb + d, pkh + i);
        cpa16(sb + OFF_VH + d, pvh + i);
    }
    CP_COMMIT();

    u32 qh[4][4];
    load_q_frags(qh, Q + ((size_t)bh * SS + q0 + qw0) * DD, gr, c);

    const int mrow0 = q0 + qw0 + gr;
    const u32* mw0 = g_maskbits + (size_t)mrow0 * (SS / 32);
    const u32* mw1 = mw0 + 8 * (SS / 32);
    const u32 bm0 = 1u << (2 * c), bm1 = 2u << (2 * c);
    const u32 bm8 = bm0 << 8,      bm9 = bm1 << 8;

    const float linv0 = g_linv[(size_t)bh * SS + q0 + qw0 + gr];
    const float linv1 = g_linv[(size_t)bh * SS + q0 + qw0 + gr + 8];

    const int rl  = ((l >> 4) & 1) * 8 + (l & 7);
    const int clk = (l >> 3) & 1;
    const u32 lkA = (u32)(rl << 7), lks = (u32)(rl & 7);
    const int rv  = ((l >> 3) & 1) * 8 + (l & 7);
    const int cv  = (l >> 4) & 1;
    const u32 lvA = (u32)(rv << 7), lvs = (u32)(rv & 7);

    // P-tile smem constants (fp16, 128 rows x 256B, XOR-swizzled 32B chunks)
    const u32 ptw = sb + PT_OFF + (u32)((qw0 + gr) * 256) + (u32)(4 * c);  // + (jp^gr)<<5
    const u32 ptr_drain = sb + PT_OFF + (u32)(qw0 * 256) + ((u32)(l & 3) << 3);
    const u32 drain_chunk = (u32)(l >> 2);   // ^ (i&7), <<5

    float oacc[8][4];
    #pragma unroll
    for (int on = 0; on < 8; on++)
        #pragma unroll
        for (int x = 0; x < 4; x++) oacc[on][x] = 0.f;

    const size_t gq = (size_t)bh * SS + q0 + qw0;

    for (int kb = 0; kb < NKB; kb++) {
        const u32 bufA = sb + (u32)((kb & 1) * BUFSZ);
        const u32 bufB = sb + (u32)(((kb + 1) & 1) * BUFSZ);
        CP_WAIT0();
        __syncthreads();
        if (kb + 1 < NKB) {
            #pragma unroll
            for (int j = 0; j < 4; j++) {
                int i = t + j * NTH;
                const size_t gi = (size_t)(kb + 1) * 1024 + i;
                u32 d = swz_dst(i);
                cpa16(bufB + d, pkh + gi);
                cpa16(bufB + OFF_VH + d, pvh + gi);
            }
            CP_COMMIT();
        }

        #pragma unroll
        for (int jp = 0; jp < 8; jp++) {
            float s0[4] = {0,0,0,0}, s1[4] = {0,0,0,0};
            #pragma unroll
            for (int ks = 0; ks < 4; ks++) {
                u32 kf[4];
                ldsm4(kf, bufA + (u32)(jp * 2048) + lkA
                          + ((((u32)(ks << 1) | clk) ^ lks) << 4));
                mma_f16(s0, qh[ks], kf[0], kf[1]);
                mma_f16(s1, qh[ks], kf[2], kf[3]);
            }

            // prefetch V frags for ops 0-1 BEFORE the exp chain (independent)
            u32 vf0[4], vf1[4];
            ldsm4t(vf0, bufA + OFF_VH + (u32)(jp * 2048) + lvA + (((u32)cv ^ lvs) << 4));
            ldsm4t(vf1, bufA + OFF_VH + (u32)(jp * 2048) + lvA + ((((u32)2 | cv) ^ lvs) << 4));

            u32 w0 = mw0[kb * 4 + (jp >> 1)];
            u32 w1 = mw1[kb * 4 + (jp >> 1)];
            u32 W0 = (jp & 1) ? (w0 >> 16) : w0;
            u32 W1 = (jp & 1) ? (w1 >> 16) : w1;

            u32 aH[4];
            {
                float a0 = (W0 & bm0) ? fmaf(s0[0], CEXP, linv0) : MASKED_ARG;
                float a1 = (W0 & bm1) ? fmaf(s0[1], CEXP, linv0) : MASKED_ARG;
                float a2 = (W1 & bm0) ? fmaf(s0[2], CEXP, linv1) : MASKED_ARG;
                float a3 = (W1 & bm1) ? fmaf(s0[3], CEXP, linv1) : MASKED_ARG;
                aH[0] = packh(ex2f(a0), ex2f(a1));
                aH[1] = packh(ex2f(a2), ex2f(a3));
            }
            {
                float a0 = (W0 & bm8) ? fmaf(s1[0], CEXP, linv0) : MASKED_ARG;
                float a1 = (W0 & bm9) ? fmaf(s1[1], CEXP, linv0) : MASKED_ARG;
                float a2 = (W1 & bm8) ? fmaf(s1[2], CEXP, linv1) : MASKED_ARG;
                float a3 = (W1 & bm9) ? fmaf(s1[3], CEXP, linv1) : MASKED_ARG;
                aH[2] = packh(ex2f(a0), ex2f(a1));
                aH[3] = packh(ex2f(a2), ex2f(a3));
            }

            // stage P into smem tile (fp16): rows qw0+gr and qw0+gr+8
            {
                u32 a = ptw + (((u32)jp ^ (u32)gr) << 5);
                asm volatile("st.shared.b32 [%0], %1;"      :: "r"(a),        "r"(aH[0]));
                asm volatile("st.shared.b32 [%0], %1;"      :: "r"(a + 16),   "r"(aH[2]));
                asm volatile("st.shared.b32 [%0], %1;"      :: "r"(a + 2048), "r"(aH[1]));
                asm volatile("st.shared.b32 [%0], %1;"      :: "r"(a + 2064), "r"(aH[3]));
            }

            mma_f16(oacc[0], aH, vf0[0], vf0[1]);
            mma_f16(oacc[1], aH, vf0[2], vf0[3]);
            u32 vf2[4], vf3[4];
            ldsm4t(vf2, bufA + OFF_VH + (u32)(jp * 2048) + lvA + ((((u32)4 | cv) ^ lvs) << 4));
            ldsm4t(vf3, bufA + OFF_VH + (u32)(jp * 2048) + lvA + ((((u32)6 | cv) ^ lvs) << 4));
            mma_f16(oacc[2], aH, vf1[0], vf1[1]);
            mma_f16(oacc[3], aH, vf1[2], vf1[3]);
            mma_f16(oacc[4], aH, vf2[0], vf2[1]);
            mma_f16(oacc[5], aH, vf2[2], vf2[3]);
            mma_f16(oacc[6], aH, vf3[0], vf3[1]);
            mma_f16(oacc[7], aH, vf3[2], vf3[3]);
        }

        // drain this warp's 16 rows of the P tile -> coalesced Prob stores
        __syncwarp();
        {
            float* pout = Prob + (gq) * SS + (size_t)kb * KT + l * 4;
            #pragma unroll
            for (int i = 0; i < 16; i++) {
                u32 addr = ptr_drain + (u32)(i * 256)
                         + ((drain_chunk ^ ((u32)i & 7)) << 5);
                uint2 hv;
                asm volatile("ld.shared.v2.b32 {%0,%1}, [%2];"
                             : "=r"(hv.x), "=r"(hv.y) : "r"(addr));
                float2 f0 = __half22float2(*reinterpret_cast<__half2*>(&hv.x));
                float2 f1 = __half22float2(*reinterpret_cast<__half2*>(&hv.y));
                __stcs((float4*)(pout + (size_t)i * SS),
                       make_float4(f0.x, f0.y, f1.x, f1.y));
            }
        }
    }

    {
        float* o0 = Out + (gq + gr) * DD + 2 * c;
        float* o1 = o0 + 8 * DD;
        #pragma unroll
        for (int on = 0; on < 8; on++) {
            *(float2*)(o0 + on * 8) = make_float2(oacc[on][0], oacc[on][1]);
            *(float2*)(o1 + on * 8) = make_float2(oacc[on][2], oacc[on][3]);
        }
    }
}

extern "C" void kernel_launch(void* const* d_in, const int* in_sizes, int n_in,
                              void* d_out, int out_size) {
    const float* q    = (const float*)d_in[0];
    const float* k    = (const float*)d_in[1];
    const float* v    = (const float*)d_in[2];
    const int*   mask = (const int*)d_in[3];

    float* out  = (float*)d_out;                          // [B,H,S,D]
    float* prob = out + (size_t)BB * HH * SS * DD;        // [B,H,S,S]

    pack_mask_kernel<<<(SS * SS / 32) / NTH, NTH>>>(mask);
    split_kv_kernel<<<(KVELEM / 8) / NTH, NTH>>>(k, v);

    cudaFuncSetAttribute(pass1_kernel,
                         cudaFuncAttributeMaxDynamicSharedMemorySize, A_SMEM);
    cudaFuncSetAttribute(pass2_kernel,
                         cudaFuncAttributeMaxDynamicSharedMemorySize, B_SMEM);

    dim3 grid(BB * HH * (SS / QT));   // 512 CTAs
    pass1_kernel<<<grid, NTH, A_SMEM>>>(q);
    pass2_kernel<<<grid, NTH, B_SMEM>>>(q, out, prob);    // launch #6 -> profiled
}